// round 10
// baseline (speedup 1.0000x reference)
#include <cuda_runtime.h>
#include <cstdint>

#define N_IMG 8192

// ---------------- scratch (device globals; no allocations) ----------------
__device__ float    g_Ppart[128 * 1024];     // partial batch sums of x
__device__ float    g_thr[20];               // per-channel BN mean (threshold)
__device__ unsigned g_b1[N_IMG * 196];       // binarized pool1: 20 channel bits per (n,py,px)
__device__ signed char g_wb2[25 * 56 * 32];  // conv2 sign(W) s8, [tap][oc(56)][c(32)], zero-init
__device__ unsigned g_wpl[500 * 40];         // linear sign(W)>0 masks (1250 bits)
__device__ unsigned g_wzl[500 * 40];         // linear W==0 masks
__device__ int      g_zflagl;
__device__ float    g_alphal[500];           // linear alpha = mean(|W|, dim=1)
__device__ unsigned g_Bp[N_IMG * 40];        // sign(+1) bit-plane into linear
__device__ unsigned g_Bn[N_IMG * 40];        // sign(-1) bit-plane into linear

// ---------------- K_pre: fused colsum + weight prep + alpha_l -------------
__global__ __launch_bounds__(256) void k_pre(const float* __restrict__ x,
                                             const float* __restrict__ w2,
                                             const float* __restrict__ wl) {
    int b = blockIdx.x, t = threadIdx.x;
    if (b < 128) {
        const float* base = x + (size_t)b * 64 * 1024 + t * 4;
        float4 acc = make_float4(0.f, 0.f, 0.f, 0.f);
        for (int i = 0; i < 64; ++i) {
            float4 v = *(const float4*)(base + (size_t)i * 1024);
            acc.x += v.x; acc.y += v.y; acc.z += v.z; acc.w += v.w;
        }
        *(float4*)(g_Ppart + b * 1024 + t * 4) = acc;
    } else if (b < 144) {
        int gid = (b - 128) * 256 + t;           // 0..4095
        if (gid < 1250) {                         // conv2 sign bytes: (oc, tap)
            int oc = gid / 25, d = gid % 25;
            for (int c = 0; c < 20; ++c) {
                float w = w2[oc * 500 + c * 25 + d];
                g_wb2[d * 1792 + oc * 32 + c] = (signed char)((w > 0.f) ? 1 : ((w < 0.f) ? -1 : 0));
            }
        }
        for (int e = gid; e < 500 * 40; e += 4096) {  // linear masks
            int j = e / 40, wi = e % 40;
            unsigned mp = 0, mz = 0;
            for (int bit = 0; bit < 32; ++bit) {
                int i = wi * 32 + bit;
                if (i < 1250) {
                    float w = wl[j * 1250 + i];
                    if (w > 0.f) mp |= 1u << bit;
                    else if (w == 0.f) mz |= 1u << bit;
                }
            }
            g_wpl[e] = mp; g_wzl[e] = mz;
            if (mz) atomicOr(&g_zflagl, 1);
        }
    } else {
        int w = (b - 144) * 8 + (t >> 5);        // row index
        int lane = t & 31;
        if (w < 500) {
            double s = 0.0;
            for (int i = lane; i < 1250; i += 32)
                s += fabs((double)wl[w * 1250 + i]);
#pragma unroll
            for (int o = 16; o; o >>= 1) s += __shfl_down_sync(0xffffffffu, s, o);
            if (lane == 0) g_alphal[w] = (float)(s / 1250.0);
        }
    }
}

// ---------------- K1b: reduce partials -> P, T[5][5], thresholds ----------
__global__ __launch_bounds__(1024) void k_thr(const float* __restrict__ w1) {
    __shared__ double Ps[1024];
    __shared__ double Ts[25];
    int t = threadIdx.x;
    double s0 = 0.0, s1 = 0.0;
    for (int i = 0; i < 128; i += 2) {
        s0 += (double)g_Ppart[i * 1024 + t];
        s1 += (double)g_Ppart[(i + 1) * 1024 + t];
    }
    Ps[t] = s0 + s1;
    __syncthreads();
    if (t < 800) {                    // 25 taps x 32 lanes, fixed shfl tree
        int g = t >> 5, lane = t & 31;
        int dy = g / 5, dx = g % 5;
        double a = 0.0;
        for (int idx = lane; idx < 784; idx += 32) {
            int i = idx / 28, j = idx % 28;
            a += Ps[(i + dy) * 32 + (j + dx)];
        }
#pragma unroll
        for (int o = 16; o; o >>= 1) a += __shfl_down_sync(0xffffffffu, a, o);
        if (lane == 0) Ts[g] = a;
    }
    __syncthreads();
    if (t < 20) {
        double d = 0.0;
        for (int k = 0; k < 25; ++k) d += (double)w1[t * 25 + k] * Ts[k];
        g_thr[t] = (float)(d / (8192.0 * 28.0 * 28.0));
    }
}

// ---------------- K2: conv1 + threshold + 2x2 pool + channel bit-pack -----
__global__ __launch_bounds__(224) void k_conv1(const float* __restrict__ x,
                                               const float* __restrict__ w1) {
    __shared__ float xs[1024];
    __shared__ float ws[20 * 28];
    __shared__ float thr_s[20];
    int n = blockIdx.x, t = threadIdx.x;
    for (int i = t; i < 1024; i += 224) xs[i] = x[(size_t)n * 1024 + i];
    for (int i = t; i < 500; i += 224) ws[(i / 25) * 28 + (i % 25)] = w1[i];
    if (t < 20) thr_s[t] = g_thr[t];
    __syncthreads();
    if (t < 196) {
        int py = t / 14, px = t % 14;
        float xp[6][6];
        const float* xb = &xs[(py * 2) * 32 + px * 2];
#pragma unroll
        for (int r = 0; r < 6; ++r) {
#pragma unroll
            for (int c2 = 0; c2 < 3; ++c2) {
                float2 v = *(const float2*)(xb + r * 32 + c2 * 2);
                xp[r][c2 * 2] = v.x; xp[r][c2 * 2 + 1] = v.y;
            }
        }
        unsigned word = 0;
#pragma unroll 1
        for (int c = 0; c < 20; ++c) {
            const float* wc = &ws[c * 28];
            float a0 = 0.f, a1 = 0.f, a2 = 0.f, a3 = 0.f;
#pragma unroll
            for (int dy = 0; dy < 5; ++dy) {
#pragma unroll
                for (int dx = 0; dx < 5; ++dx) {
                    float w = wc[dy * 5 + dx];
                    a0 = fmaf(w, xp[dy][dx],         a0);
                    a1 = fmaf(w, xp[dy][dx + 1],     a1);
                    a2 = fmaf(w, xp[dy + 1][dx],     a2);
                    a3 = fmaf(w, xp[dy + 1][dx + 1], a3);
                }
            }
            float m = fmaxf(fmaxf(a0, a1), fmaxf(a2, a3));
            if (m > thr_s[c]) word |= (1u << c);
        }
        g_b1[n * 196 + t] = word;
    }
}

// ---------------- K3: conv2 as s8 IMMA GEMM, tap-per-K-step ---------------
// smem layout (dynamic):
//   [0, 50176)           vbuf  s32 [2][112][56]
//   [50176, 94976)       WBs   s8  [25][56][32]
//   [94976, 109088)      Ms    u8  [2][196*36]  (20 ch bytes + 12 zero + 4 pad)
//   [109088, 111648)     sPN   u8  [2][1280]
#define C2_SMEM 111648
__global__ __launch_bounds__(448) void k_conv2(const unsigned* __restrict__ dummy) {
    extern __shared__ __align__(16) unsigned char cs[];
    int*           vbuf = (int*)cs;
    signed char*   WBs  = (signed char*)(cs + 50176);
    unsigned char* Ms   = cs + 94976;
    unsigned char* sPN  = cs + 109088;
    int n0 = blockIdx.x * 2, t = threadIdx.x;
    // 1) stage weights
    for (int i = t; i < 44800 / 4; i += 448)
        ((unsigned*)WBs)[i] = ((const unsigned*)g_wb2)[i];
    // 2) expand activation bits -> byte map (20 bytes + 12 zeros per pixel)
    for (int i = t; i < 2 * 196; i += 448) {
        int img = i / 196, p = i % 196;
        unsigned bv = g_b1[(size_t)(n0 + img) * 196 + p];
        unsigned char* e = Ms + img * 7056 + p * 36;
#pragma unroll
        for (int j = 0; j < 5; ++j) {
            unsigned v = (((bv >> (4 * j)) & 0xFu) * 0x00204081u) & 0x01010101u;
            *(unsigned*)(e + 4 * j) = v;
        }
        *(unsigned*)(e + 20) = 0; *(unsigned*)(e + 24) = 0;
        *(unsigned*)(e + 28) = 0; *(unsigned*)(e + 32) = 0;
    }
    if (t < 2 * 30) sPN[(t / 30) * 1280 + 1250 + (t % 30)] = 0;
    __syncthreads();
    // 3) mainloop: warp = (img, Mtile); 25 taps as K-steps
    {
        int wid = t >> 5, lane = t & 31;
        int img = wid & 1, mt = wid >> 1;             // 14 warps
        int g = lane >> 2, tid4 = (lane & 3) * 4;
        int o0 = mt * 16 + g, o1 = o0 + 8;
        int p0 = min(o0, 99), p1 = min(o1, 99);       // clamp for addressing only
        const unsigned char* A0 =
            Ms + img * 7056 + ((p0 / 10) * 14 + (p0 % 10)) * 36 + tid4;
        const unsigned char* A1 =
            Ms + img * 7056 + ((p1 / 10) * 14 + (p1 % 10)) * 36 + tid4;
        const signed char* WBg = WBs + g * 32 + tid4;
        int acc[7][4];
#pragma unroll
        for (int n = 0; n < 7; ++n) { acc[n][0] = 0; acc[n][1] = 0; acc[n][2] = 0; acc[n][3] = 0; }
#pragma unroll
        for (int dy = 0; dy < 5; ++dy) {
#pragma unroll
            for (int dx = 0; dx < 5; ++dx) {
                int moff = (dy * 14 + dx) * 36;
                unsigned a0 = *(const unsigned*)(A0 + moff);
                unsigned a2 = *(const unsigned*)(A0 + moff + 16);
                unsigned a1 = *(const unsigned*)(A1 + moff);
                unsigned a3 = *(const unsigned*)(A1 + moff + 16);
                const signed char* wb = WBg + (dy * 5 + dx) * 1792;
#pragma unroll
                for (int n = 0; n < 7; ++n) {
                    unsigned b0 = *(const unsigned*)(wb + n * 256);
                    unsigned b1 = *(const unsigned*)(wb + n * 256 + 16);
                    asm volatile(
                        "mma.sync.aligned.m16n8k32.row.col.s32.s8.s8.s32 "
                        "{%0,%1,%2,%3}, {%4,%5,%6,%7}, {%8,%9}, {%0,%1,%2,%3};"
                        : "+r"(acc[n][0]), "+r"(acc[n][1]), "+r"(acc[n][2]), "+r"(acc[n][3])
                        : "r"(a0), "r"(a1), "r"(a2), "r"(a3), "r"(b0), "r"(b1));
                }
            }
        }
        int* vb = vbuf + img * 112 * 56;
        int colb = (lane & 3) * 2;
#pragma unroll
        for (int n = 0; n < 7; ++n) {
            int col = n * 8 + colb;
            if (o0 < 100) { vb[o0 * 56 + col] = acc[n][0]; vb[o0 * 56 + col + 1] = acc[n][1]; }
            if (o1 < 100) { vb[o1 * 56 + col] = acc[n][2]; vb[o1 * 56 + col + 1] = acc[n][3]; }
        }
    }
    __syncthreads();
    // 4) 2x2 maxpool + sign bytes
    for (int i = t; i < 2 * 1250; i += 448) {
        int img = i / 1250, u = i % 1250;
        int oc = u / 25, p = u % 25, py = p / 5, px = p % 5;
        const int* vb = vbuf + img * 112 * 56;
        int r0 = (2 * py) * 10 + 2 * px;
        int v00 = vb[r0 * 56 + oc],        v01 = vb[(r0 + 1) * 56 + oc];
        int v10 = vb[(r0 + 10) * 56 + oc], v11 = vb[(r0 + 11) * 56 + oc];
        int best = max(max(v00, v01), max(v10, v11));
        sPN[img * 1280 + oc * 25 + p] =
            (unsigned char)((best > 0 ? 1 : 0) | (best < 0 ? 2 : 0));
    }
    __syncthreads();
    // 5) byte planes -> bit planes
    if (t < 2 * 40) {
        int img = t / 40, wi = t % 40;
        const unsigned* src = (const unsigned*)(sPN + img * 1280) + wi * 8;
        unsigned P = 0, N = 0;
#pragma unroll
        for (int j = 0; j < 8; ++j) {
            unsigned b = src[j];
            P |= ((((b & 0x01010101u) * 0x00204081u) >> 21) & 0xFu) << (4 * j);
            N |= (((((b >> 1) & 0x01010101u) * 0x00204081u) >> 21) & 0xFu) << (4 * j);
        }
        g_Bp[(size_t)(n0 + img) * 40 + wi] = P;
        g_Bn[(size_t)(n0 + img) * 40 + wi] = N;
    }
    (void)dummy;
}

// ---------------- K4: binary linear (XNOR-LOP3) + clip + fc, 16 imgs ------
#define D_IMGS 16
__global__ __launch_bounds__(512) void k_dense(const float* __restrict__ fcw,
                                               const float* __restrict__ fcb,
                                               float* __restrict__ out) {
    extern __shared__ unsigned sm[];
    unsigned* Ws  = sm;                       // 500*41 (padded, conflict-free)
    unsigned* Bps = Ws + 500 * 41;            // D*40  sign bit-plane (+1)
    unsigned* Bns = Bps + D_IMGS * 40;        // D*40  sign bit-plane (-1), zf path only
    unsigned* Us  = Bns + D_IMGS * 40;        // D*40  nonzero mask = Bp|Bn
    int*      pcU = (int*)(Us + D_IMGS * 40); // D
    float*    hs  = (float*)(pcU + D_IMGS);   // D*500
    int t = threadIdx.x;
    int n0 = blockIdx.x * D_IMGS;
    for (int i = t; i < 500 * 40; i += 512) Ws[(i / 40) * 41 + (i % 40)] = g_wpl[i];
    for (int i = t; i < D_IMGS * 40; i += 512) {
        int img = i / 40, wi = i % 40;
        unsigned bp = g_Bp[(size_t)(n0 + img) * 40 + wi];
        unsigned bn = g_Bn[(size_t)(n0 + img) * 40 + wi];
        Bps[img * 40 + wi] = bp;
        Bns[img * 40 + wi] = bn;
        Us[img * 40 + wi]  = bp | bn;
    }
    __syncthreads();
    if (t < D_IMGS) {
        int s = 0;
        for (int k = 0; k < 40; ++k) s += __popc(Us[t * 40 + k]);
        pcU[t] = s;
    }
    __syncthreads();
    int zf = g_zflagl;
    for (int j = t; j < 500; j += 512) {
        unsigned wr[40];
#pragma unroll
        for (int k = 0; k < 40; ++k) wr[k] = Ws[j * 41 + k];
        float al = g_alphal[j];
#pragma unroll 1
        for (int img = 0; img < D_IMGS; ++img) {
            int m = 0;
#pragma unroll
            for (int k = 0; k < 40; ++k) {
                m += __popc((~(Bps[img * 40 + k] ^ wr[k])) & Us[img * 40 + k]);
            }
            int vi = 2 * m - pcU[img];
            if (zf) {  // uniform, never taken with this dataset
                int cp = 0, cn = 0;
                for (int k = 0; k < 40; ++k) {
                    unsigned z = g_wzl[j * 40 + k];
                    cp += __popc(Bps[img * 40 + k] & z);
                    cn += __popc(Bns[img * 40 + k] & z);
                }
                vi += cp - cn;
            }
            float h = fminf(fmaxf((float)vi * al, -1.f), 1.f);
            hs[img * 500 + j] = h;
        }
    }
    __syncthreads();
    int w = t >> 5, lane = t & 31;   // warp w -> image w
    for (int lg = 0; lg < 10; ++lg) {
        float p = 0.f;
        for (int j = lane; j < 500; j += 32)
            p += hs[w * 500 + j] * __ldg(&fcw[lg * 500 + j]);
#pragma unroll
        for (int o = 16; o; o >>= 1) p += __shfl_down_sync(0xffffffffu, p, o);
        if (lane == 0) out[(size_t)(n0 + w) * 10 + lg] = p + fcb[lg];
    }
}

// ---------------- launch ---------------------------------------------------
extern "C" void kernel_launch(void* const* d_in, const int* in_sizes, int n_in,
                              void* d_out, int out_size) {
    const float* x   = (const float*)d_in[0];
    const float* w1  = (const float*)d_in[1];
    const float* w2  = (const float*)d_in[2];
    const float* wl  = (const float*)d_in[3];
    const float* fcw = (const float*)d_in[4];
    const float* fcb = (const float*)d_in[5];
    float* out = (float*)d_out;

    size_t dense_smem = (500 * 41 + D_IMGS * 40 * 3 + D_IMGS) * 4 + D_IMGS * 500 * 4;
    cudaFuncSetAttribute(k_dense, cudaFuncAttributeMaxDynamicSharedMemorySize,
                         (int)dense_smem);
    cudaFuncSetAttribute(k_conv2, cudaFuncAttributeMaxDynamicSharedMemorySize,
                         C2_SMEM);

    k_pre<<<207, 256>>>(x, w2, wl);
    k_thr<<<1, 1024>>>(w1);
    k_conv1<<<8192, 224>>>(x, w1);
    k_conv2<<<N_IMG / 2, 448, C2_SMEM>>>(nullptr);
    k_dense<<<N_IMG / D_IMGS, 512, dense_smem>>>(fcw, fcb, out);
}

// round 11
// speedup vs baseline: 1.3147x; 1.3147x over previous
#include <cuda_runtime.h>
#include <cstdint>

#define N_IMG 8192
#define MMA_IMGS 3328                 // images on the IMMA/tensor stream
#define SC_IMGS  (N_IMG - MMA_IMGS)  // images on the scalar stream

// ---------------- scratch (device globals; no allocations) ----------------
__device__ float    g_Ppart[128 * 1024];     // partial batch sums of x
__device__ float    g_thr[20];               // per-channel BN mean (threshold)
__device__ unsigned g_b1[N_IMG * 196];       // binarized pool1: 20 channel bits per (n,py,px)
__device__ unsigned g_wp2[50 * 25];          // conv2 sign(W)>0 masks (20 bits over c)
__device__ unsigned g_wp2p[50 * 5 * 8];      // conv2 masks, 8-word padded rows
__device__ unsigned g_wz2[50 * 25];          // conv2 W==0 masks
__device__ int      g_zflag2;                // any zero conv2 weight
__device__ signed char g_wb2[25 * 56 * 32];  // conv2 sign(W) s8, [tap][oc(56)][c(32)], zero-init
__device__ unsigned g_wpl[500 * 40];         // linear sign(W)>0 masks (1250 bits)
__device__ unsigned g_wzl[500 * 40];         // linear W==0 masks
__device__ int      g_zflagl;
__device__ float    g_alphal[500];           // linear alpha = mean(|W|, dim=1)
__device__ unsigned g_Bp[N_IMG * 40];        // sign(+1) bit-plane into linear
__device__ unsigned g_Bn[N_IMG * 40];        // sign(-1) bit-plane into linear

// ---------------- K_pre: fused colsum + weight prep + alpha_l -------------
__global__ __launch_bounds__(256) void k_pre(const float* __restrict__ x,
                                             const float* __restrict__ w2,
                                             const float* __restrict__ wl) {
    int b = blockIdx.x, t = threadIdx.x;
    if (b < 128) {
        const float* base = x + (size_t)b * 64 * 1024 + t * 4;
        float4 acc = make_float4(0.f, 0.f, 0.f, 0.f);
        for (int i = 0; i < 64; ++i) {
            float4 v = *(const float4*)(base + (size_t)i * 1024);
            acc.x += v.x; acc.y += v.y; acc.z += v.z; acc.w += v.w;
        }
        *(float4*)(g_Ppart + b * 1024 + t * 4) = acc;
    } else if (b < 144) {
        int gid = (b - 128) * 256 + t;           // 0..4095
        if (gid < 1250) {                         // conv2 masks + s8 bytes
            int oc = gid / 25, d = gid % 25;
            int dy = d / 5, dx = d % 5;
            unsigned mp = 0, mz = 0;
            for (int c = 0; c < 20; ++c) {
                float w = w2[oc * 500 + c * 25 + d];
                if (w > 0.f) mp |= 1u << c;
                else if (w == 0.f) mz |= 1u << c;
                g_wb2[d * 1792 + oc * 32 + c] =
                    (signed char)((w > 0.f) ? 1 : ((w < 0.f) ? -1 : 0));
            }
            g_wp2[gid] = mp; g_wz2[gid] = mz;
            g_wp2p[(oc * 5 + dy) * 8 + dx] = mp;
            if (dx == 0) {
                g_wp2p[(oc * 5 + dy) * 8 + 5] = 0;
                g_wp2p[(oc * 5 + dy) * 8 + 6] = 0;
                g_wp2p[(oc * 5 + dy) * 8 + 7] = 0;
            }
            if (mz) atomicOr(&g_zflag2, 1);
        }
        for (int e = gid; e < 500 * 40; e += 4096) {  // linear masks
            int j = e / 40, wi = e % 40;
            unsigned mp = 0, mz = 0;
            for (int bit = 0; bit < 32; ++bit) {
                int i = wi * 32 + bit;
                if (i < 1250) {
                    float w = wl[j * 1250 + i];
                    if (w > 0.f) mp |= 1u << bit;
                    else if (w == 0.f) mz |= 1u << bit;
                }
            }
            g_wpl[e] = mp; g_wzl[e] = mz;
            if (mz) atomicOr(&g_zflagl, 1);
        }
    } else {
        int w = (b - 144) * 8 + (t >> 5);        // row index
        int lane = t & 31;
        if (w < 500) {
            double s = 0.0;
            for (int i = lane; i < 1250; i += 32)
                s += fabs((double)wl[w * 1250 + i]);
#pragma unroll
            for (int o = 16; o; o >>= 1) s += __shfl_down_sync(0xffffffffu, s, o);
            if (lane == 0) g_alphal[w] = (float)(s / 1250.0);
        }
    }
}

// ---------------- K1b: reduce partials -> P, T[5][5], thresholds ----------
__global__ __launch_bounds__(1024) void k_thr(const float* __restrict__ w1) {
    __shared__ double Ps[1024];
    __shared__ double Ts[25];
    int t = threadIdx.x;
    double s0 = 0.0, s1 = 0.0;
    for (int i = 0; i < 128; i += 2) {
        s0 += (double)g_Ppart[i * 1024 + t];
        s1 += (double)g_Ppart[(i + 1) * 1024 + t];
    }
    Ps[t] = s0 + s1;
    __syncthreads();
    if (t < 800) {
        int g = t >> 5, lane = t & 31;
        int dy = g / 5, dx = g % 5;
        double a = 0.0;
        for (int idx = lane; idx < 784; idx += 32) {
            int i = idx / 28, j = idx % 28;
            a += Ps[(i + dy) * 32 + (j + dx)];
        }
#pragma unroll
        for (int o = 16; o; o >>= 1) a += __shfl_down_sync(0xffffffffu, a, o);
        if (lane == 0) Ts[g] = a;
    }
    __syncthreads();
    if (t < 20) {
        double d = 0.0;
        for (int k = 0; k < 25; ++k) d += (double)w1[t * 25 + k] * Ts[k];
        g_thr[t] = (float)(d / (8192.0 * 28.0 * 28.0));
    }
}

// ---------------- K2: conv1 + threshold + 2x2 pool + channel bit-pack -----
__global__ __launch_bounds__(224) void k_conv1(const float* __restrict__ x,
                                               const float* __restrict__ w1,
                                               int n_base) {
    __shared__ float xs[1024];
    __shared__ float ws[20 * 28];
    __shared__ float thr_s[20];
    int n = n_base + blockIdx.x, t = threadIdx.x;
    for (int i = t; i < 1024; i += 224) xs[i] = x[(size_t)n * 1024 + i];
    for (int i = t; i < 500; i += 224) ws[(i / 25) * 28 + (i % 25)] = w1[i];
    if (t < 20) thr_s[t] = g_thr[t];
    __syncthreads();
    if (t < 196) {
        int py = t / 14, px = t % 14;
        float xp[6][6];
        const float* xb = &xs[(py * 2) * 32 + px * 2];
#pragma unroll
        for (int r = 0; r < 6; ++r) {
#pragma unroll
            for (int c2 = 0; c2 < 3; ++c2) {
                float2 v = *(const float2*)(xb + r * 32 + c2 * 2);
                xp[r][c2 * 2] = v.x; xp[r][c2 * 2 + 1] = v.y;
            }
        }
        unsigned word = 0;
#pragma unroll 1
        for (int c = 0; c < 20; ++c) {
            const float* wc = &ws[c * 28];
            float a0 = 0.f, a1 = 0.f, a2 = 0.f, a3 = 0.f;
#pragma unroll
            for (int dy = 0; dy < 5; ++dy) {
#pragma unroll
                for (int dx = 0; dx < 5; ++dx) {
                    float w = wc[dy * 5 + dx];
                    a0 = fmaf(w, xp[dy][dx],         a0);
                    a1 = fmaf(w, xp[dy][dx + 1],     a1);
                    a2 = fmaf(w, xp[dy + 1][dx],     a2);
                    a3 = fmaf(w, xp[dy + 1][dx + 1], a3);
                }
            }
            float m = fmaxf(fmaxf(a0, a1), fmaxf(a2, a3));
            if (m > thr_s[c]) word |= (1u << c);
        }
        g_b1[n * 196 + t] = word;
    }
}

// ---------------- K3a: scalar XNOR conv2 (R8-best) ------------------------
#define C2_IMGS 2
#define ROWW 20
__global__ __launch_bounds__(256) void k_conv2_sc(int n_base) {
    __shared__ __align__(16) unsigned BsA[C2_IMGS * 14 * ROWW];
    __shared__ __align__(16) unsigned BsB[C2_IMGS * 14 * ROWW];
    __shared__ int PB[C2_IMGS][100];
    __shared__ __align__(16) unsigned Wps[50 * 5 * 8];
    __shared__ __align__(16) unsigned char sPN[C2_IMGS][1280];
    int n0 = n_base + blockIdx.x * C2_IMGS, t = threadIdx.x;
    for (int i = t; i < C2_IMGS * 196; i += 256) {
        int img = i / 196, p = i % 196;
        int y = p / 14, xx = p % 14;
        unsigned bv = g_b1[(size_t)(n0 + img) * 196 + p];
        BsA[img * 14 * ROWW + y * ROWW + xx] = bv;
        if (xx >= 2) BsB[img * 14 * ROWW + y * ROWW + xx - 2] = bv;
    }
    for (int i = t; i < 50 * 5 * 8; i += 256) Wps[i] = g_wp2p[i];
    if (t < C2_IMGS * 30) sPN[t / 30][1250 + (t % 30)] = 0;
    __syncthreads();
    for (int i = t; i < C2_IMGS * 100; i += 256) {
        int img = i / 100, p = i % 100;
        int y = p / 10, xx = p % 10;
        const unsigned* B = &BsA[img * 14 * ROWW];
        int s = 0;
#pragma unroll
        for (int dy = 0; dy < 5; ++dy)
#pragma unroll
            for (int dx = 0; dx < 5; ++dx)
                s += __popc(B[(y + dy) * ROWW + xx + dx]);
        PB[img][p] = s;
    }
    __syncthreads();
    int zf = g_zflag2;
    if (t < 250) {
        int oc = t / 5, cx = t % 5;
        int odd = cx & 1;
        const unsigned* P0 = odd ? BsB : BsA;
        int colbase = odd ? (2 * cx - 2) : (2 * cx);
        unsigned W[25];
#pragma unroll
        for (int j = 0; j < 5; ++j) {
            uint4 wq = *(const uint4*)(&Wps[oc * 40 + j * 8]);
            W[j * 5] = wq.x; W[j * 5 + 1] = wq.y; W[j * 5 + 2] = wq.z; W[j * 5 + 3] = wq.w;
            W[j * 5 + 4] = Wps[oc * 40 + j * 8 + 4];
        }
#pragma unroll 1
        for (int r = 0; r < 5; ++r) {
#pragma unroll 1
            for (int img = 0; img < C2_IMGS; ++img) {
                const unsigned* bp0 = P0 + img * 14 * ROWW + (2 * r) * ROWW + colbase;
                int a00 = 0, a01 = 0, a10 = 0, a11 = 0;
#pragma unroll
                for (int rr = 0; rr < 6; ++rr) {
                    const unsigned* bp = bp0 + rr * ROWW;
                    uint4 q = *(const uint4*)bp;
                    uint2 d2 = *(const uint2*)(bp + 4);
                    unsigned p0 = q.x, p1 = q.y, p2 = q.z, p3 = q.w, p4 = d2.x, p5 = d2.y;
                    if (rr < 5) {
                        a00 += __popc(p0 & W[rr * 5]) + __popc(p1 & W[rr * 5 + 1])
                             + __popc(p2 & W[rr * 5 + 2]) + __popc(p3 & W[rr * 5 + 3])
                             + __popc(p4 & W[rr * 5 + 4]);
                        a01 += __popc(p1 & W[rr * 5]) + __popc(p2 & W[rr * 5 + 1])
                             + __popc(p3 & W[rr * 5 + 2]) + __popc(p4 & W[rr * 5 + 3])
                             + __popc(p5 & W[rr * 5 + 4]);
                    }
                    if (rr >= 1) {
                        a10 += __popc(p0 & W[(rr - 1) * 5]) + __popc(p1 & W[(rr - 1) * 5 + 1])
                             + __popc(p2 & W[(rr - 1) * 5 + 2]) + __popc(p3 & W[(rr - 1) * 5 + 3])
                             + __popc(p4 & W[(rr - 1) * 5 + 4]);
                        a11 += __popc(p1 & W[(rr - 1) * 5]) + __popc(p2 & W[(rr - 1) * 5 + 1])
                             + __popc(p3 & W[(rr - 1) * 5 + 2]) + __popc(p4 & W[(rr - 1) * 5 + 3])
                             + __popc(p5 & W[(rr - 1) * 5 + 4]);
                    }
                }
                int v00 = 2 * a00 - PB[img][(2 * r) * 10 + 2 * cx];
                int v01 = 2 * a01 - PB[img][(2 * r) * 10 + 2 * cx + 1];
                int v10 = 2 * a10 - PB[img][(2 * r + 1) * 10 + 2 * cx];
                int v11 = 2 * a11 - PB[img][(2 * r + 1) * 10 + 2 * cx + 1];
                if (zf) {  // uniform, never taken with this dataset
                    const unsigned* B = &BsA[img * 14 * ROWW + (2 * r) * ROWW + 2 * cx];
                    int z00 = 0, z01 = 0, z10 = 0, z11 = 0;
                    for (int dy = 0; dy < 5; ++dy)
                        for (int dx = 0; dx < 5; ++dx) {
                            unsigned wz = g_wz2[oc * 25 + dy * 5 + dx];
                            z00 += __popc(B[dy * ROWW + dx] & wz);
                            z01 += __popc(B[dy * ROWW + dx + 1] & wz);
                            z10 += __popc(B[(dy + 1) * ROWW + dx] & wz);
                            z11 += __popc(B[(dy + 1) * ROWW + dx + 1] & wz);
                        }
                    v00 += z00; v01 += z01; v10 += z10; v11 += z11;
                }
                int best = max(max(v00, v01), max(v10, v11));
                sPN[img][oc * 25 + r * 5 + cx] =
                    (unsigned char)((best > 0 ? 1 : 0) | (best < 0 ? 2 : 0));
            }
        }
    }
    __syncthreads();
    if (t < C2_IMGS * 40) {
        int img = t / 40, wi = t % 40;
        const unsigned* src = (const unsigned*)&sPN[img][0] + wi * 8;
        unsigned P = 0, N = 0;
#pragma unroll
        for (int j = 0; j < 8; ++j) {
            unsigned b = src[j];
            P |= ((((b & 0x01010101u) * 0x00204081u) >> 21) & 0xFu) << (4 * j);
            N |= (((((b >> 1) & 0x01010101u) * 0x00204081u) >> 21) & 0xFu) << (4 * j);
        }
        g_Bp[(size_t)(n0 + img) * 40 + wi] = P;
        g_Bn[(size_t)(n0 + img) * 40 + wi] = N;
    }
}

// ---------------- K3b: IMMA conv2 (tensor pipe) ---------------------------
#define C2_SMEM 111648
__global__ __launch_bounds__(448) void k_conv2_mma(int n_base) {
    extern __shared__ __align__(16) unsigned char cs[];
    int*           vbuf = (int*)cs;
    signed char*   WBs  = (signed char*)(cs + 50176);
    unsigned char* Ms   = cs + 94976;
    unsigned char* sPN  = cs + 109088;
    int n0 = n_base + blockIdx.x * 2, t = threadIdx.x;
    for (int i = t; i < 44800 / 4; i += 448)
        ((unsigned*)WBs)[i] = ((const unsigned*)g_wb2)[i];
    for (int i = t; i < 2 * 196; i += 448) {
        int img = i / 196, p = i % 196;
        unsigned bv = g_b1[(size_t)(n0 + img) * 196 + p];
        unsigned char* e = Ms + img * 7056 + p * 36;
#pragma unroll
        for (int j = 0; j < 5; ++j) {
            unsigned v = (((bv >> (4 * j)) & 0xFu) * 0x00204081u) & 0x01010101u;
            *(unsigned*)(e + 4 * j) = v;
        }
        *(unsigned*)(e + 20) = 0; *(unsigned*)(e + 24) = 0;
        *(unsigned*)(e + 28) = 0; *(unsigned*)(e + 32) = 0;
    }
    if (t < 2 * 30) sPN[(t / 30) * 1280 + 1250 + (t % 30)] = 0;
    __syncthreads();
    {
        int wid = t >> 5, lane = t & 31;
        int img = wid & 1, mt = wid >> 1;
        int g = lane >> 2, tid4 = (lane & 3) * 4;
        int o0 = mt * 16 + g, o1 = o0 + 8;
        int p0 = min(o0, 99), p1 = min(o1, 99);
        const unsigned char* A0 =
            Ms + img * 7056 + ((p0 / 10) * 14 + (p0 % 10)) * 36 + tid4;
        const unsigned char* A1 =
            Ms + img * 7056 + ((p1 / 10) * 14 + (p1 % 10)) * 36 + tid4;
        const signed char* WBg = WBs + g * 32 + tid4;
        int acc[7][4];
#pragma unroll
        for (int n = 0; n < 7; ++n) { acc[n][0] = 0; acc[n][1] = 0; acc[n][2] = 0; acc[n][3] = 0; }
#pragma unroll
        for (int dy = 0; dy < 5; ++dy) {
#pragma unroll
            for (int dx = 0; dx < 5; ++dx) {
                int moff = (dy * 14 + dx) * 36;
                unsigned a0 = *(const unsigned*)(A0 + moff);
                unsigned a2 = *(const unsigned*)(A0 + moff + 16);
                unsigned a1 = *(const unsigned*)(A1 + moff);
                unsigned a3 = *(const unsigned*)(A1 + moff + 16);
                const signed char* wb = WBg + (dy * 5 + dx) * 1792;
#pragma unroll
                for (int n = 0; n < 7; ++n) {
                    unsigned b0 = *(const unsigned*)(wb + n * 256);
                    unsigned b1 = *(const unsigned*)(wb + n * 256 + 16);
                    asm volatile(
                        "mma.sync.aligned.m16n8k32.row.col.s32.s8.s8.s32 "
                        "{%0,%1,%2,%3}, {%4,%5,%6,%7}, {%8,%9}, {%0,%1,%2,%3};"
                        : "+r"(acc[n][0]), "+r"(acc[n][1]), "+r"(acc[n][2]), "+r"(acc[n][3])
                        : "r"(a0), "r"(a1), "r"(a2), "r"(a3), "r"(b0), "r"(b1));
                }
            }
        }
        int* vb = vbuf + img * 112 * 56;
        int colb = (lane & 3) * 2;
#pragma unroll
        for (int n = 0; n < 7; ++n) {
            int col = n * 8 + colb;
            if (o0 < 100) { vb[o0 * 56 + col] = acc[n][0]; vb[o0 * 56 + col + 1] = acc[n][1]; }
            if (o1 < 100) { vb[o1 * 56 + col] = acc[n][2]; vb[o1 * 56 + col + 1] = acc[n][3]; }
        }
    }
    __syncthreads();
    for (int i = t; i < 2 * 1250; i += 448) {
        int img = i / 1250, u = i % 1250;
        int oc = u / 25, p = u % 25, py = p / 5, px = p % 5;
        const int* vb = vbuf + img * 112 * 56;
        int r0 = (2 * py) * 10 + 2 * px;
        int v00 = vb[r0 * 56 + oc],        v01 = vb[(r0 + 1) * 56 + oc];
        int v10 = vb[(r0 + 10) * 56 + oc], v11 = vb[(r0 + 11) * 56 + oc];
        int best = max(max(v00, v01), max(v10, v11));
        sPN[img * 1280 + oc * 25 + p] =
            (unsigned char)((best > 0 ? 1 : 0) | (best < 0 ? 2 : 0));
    }
    __syncthreads();
    if (t < 2 * 40) {
        int img = t / 40, wi = t % 40;
        const unsigned* src = (const unsigned*)(sPN + img * 1280) + wi * 8;
        unsigned P = 0, N = 0;
#pragma unroll
        for (int j = 0; j < 8; ++j) {
            unsigned b = src[j];
            P |= ((((b & 0x01010101u) * 0x00204081u) >> 21) & 0xFu) << (4 * j);
            N |= (((((b >> 1) & 0x01010101u) * 0x00204081u) >> 21) & 0xFu) << (4 * j);
        }
        g_Bp[(size_t)(n0 + img) * 40 + wi] = P;
        g_Bn[(size_t)(n0 + img) * 40 + wi] = N;
    }
}

// ---------------- K4: binary linear (XNOR-LOP3) + clip + fc, 16 imgs ------
#define D_IMGS 16
__global__ __launch_bounds__(512) void k_dense(const float* __restrict__ fcw,
                                               const float* __restrict__ fcb,
                                               float* __restrict__ out) {
    extern __shared__ unsigned sm[];
    unsigned* Ws  = sm;
    unsigned* Bps = Ws + 500 * 41;
    unsigned* Bns = Bps + D_IMGS * 40;
    unsigned* Us  = Bns + D_IMGS * 40;
    int*      pcU = (int*)(Us + D_IMGS * 40);
    float*    hs  = (float*)(pcU + D_IMGS);
    int t = threadIdx.x;
    int n0 = blockIdx.x * D_IMGS;
    for (int i = t; i < 500 * 40; i += 512) Ws[(i / 40) * 41 + (i % 40)] = g_wpl[i];
    for (int i = t; i < D_IMGS * 40; i += 512) {
        int img = i / 40, wi = i % 40;
        unsigned bp = g_Bp[(size_t)(n0 + img) * 40 + wi];
        unsigned bn = g_Bn[(size_t)(n0 + img) * 40 + wi];
        Bps[img * 40 + wi] = bp;
        Bns[img * 40 + wi] = bn;
        Us[img * 40 + wi]  = bp | bn;
    }
    __syncthreads();
    if (t < D_IMGS) {
        int s = 0;
        for (int k = 0; k < 40; ++k) s += __popc(Us[t * 40 + k]);
        pcU[t] = s;
    }
    __syncthreads();
    int zf = g_zflagl;
    for (int j = t; j < 500; j += 512) {
        unsigned wr[40];
#pragma unroll
        for (int k = 0; k < 40; ++k) wr[k] = Ws[j * 41 + k];
        float al = g_alphal[j];
#pragma unroll 1
        for (int img = 0; img < D_IMGS; ++img) {
            int m = 0;
#pragma unroll
            for (int k = 0; k < 40; ++k) {
                m += __popc((~(Bps[img * 40 + k] ^ wr[k])) & Us[img * 40 + k]);
            }
            int vi = 2 * m - pcU[img];
            if (zf) {  // uniform, never taken with this dataset
                int cp = 0, cn = 0;
                for (int k = 0; k < 40; ++k) {
                    unsigned z = g_wzl[j * 40 + k];
                    cp += __popc(Bps[img * 40 + k] & z);
                    cn += __popc(Bns[img * 40 + k] & z);
                }
                vi += cp - cn;
            }
            float h = fminf(fmaxf((float)vi * al, -1.f), 1.f);
            hs[img * 500 + j] = h;
        }
    }
    __syncthreads();
    int w = t >> 5, lane = t & 31;
    for (int lg = 0; lg < 10; ++lg) {
        float p = 0.f;
        for (int j = lane; j < 500; j += 32)
            p += hs[w * 500 + j] * __ldg(&fcw[lg * 500 + j]);
#pragma unroll
        for (int o = 16; o; o >>= 1) p += __shfl_down_sync(0xffffffffu, p, o);
        if (lane == 0) out[(size_t)(n0 + w) * 10 + lg] = p + fcb[lg];
    }
}

// ---------------- stream/event setup (static init, before any capture) ----
static cudaStream_t g_s2 = nullptr;
static cudaEvent_t  g_ef = nullptr, g_ej = nullptr;
static struct _StreamInit {
    _StreamInit() {
        cudaStreamCreateWithFlags(&g_s2, cudaStreamNonBlocking);
        cudaEventCreateWithFlags(&g_ef, cudaEventDisableTiming);
        cudaEventCreateWithFlags(&g_ej, cudaEventDisableTiming);
    }
} g_stream_init;

// ---------------- launch ---------------------------------------------------
extern "C" void kernel_launch(void* const* d_in, const int* in_sizes, int n_in,
                              void* d_out, int out_size) {
    const float* x   = (const float*)d_in[0];
    const float* w1  = (const float*)d_in[1];
    const float* w2  = (const float*)d_in[2];
    const float* wl  = (const float*)d_in[3];
    const float* fcw = (const float*)d_in[4];
    const float* fcb = (const float*)d_in[5];
    float* out = (float*)d_out;

    size_t dense_smem = (500 * 41 + D_IMGS * 40 * 3 + D_IMGS) * 4 + D_IMGS * 500 * 4;
    cudaFuncSetAttribute(k_dense, cudaFuncAttributeMaxDynamicSharedMemorySize,
                         (int)dense_smem);
    cudaFuncSetAttribute(k_conv2_mma, cudaFuncAttributeMaxDynamicSharedMemorySize,
                         C2_SMEM);

    k_pre<<<207, 256>>>(x, w2, wl);
    k_thr<<<1, 1024>>>(w1);

    // conv1 for the IMMA chunk, then fork the tensor-pipe stream
    k_conv1<<<MMA_IMGS, 224>>>(x, w1, 0);
    cudaEventRecord(g_ef, 0);
    cudaStreamWaitEvent(g_s2, g_ef, 0);
    k_conv2_mma<<<MMA_IMGS / 2, 448, C2_SMEM, g_s2>>>(0);
    cudaEventRecord(g_ej, g_s2);

    // main stream: remaining conv1 + scalar conv2 (overlaps with IMMA)
    k_conv1<<<SC_IMGS, 224>>>(x, w1, MMA_IMGS);
    k_conv2_sc<<<SC_IMGS / C2_IMGS, 256>>>(MMA_IMGS);

    // join, then dense
    cudaStreamWaitEvent(0, g_ej, 0);
    k_dense<<<N_IMG / D_IMGS, 512, dense_smem>>>(fcw, fcb, out);
}

// round 12
// speedup vs baseline: 1.7898x; 1.3614x over previous
#include <cuda_runtime.h>
#include <cstdint>

#define N_IMG 8192

// ---------------- scratch (device globals; no allocations) ----------------
__device__ float    g_Ppart[128 * 1024];     // partial batch sums of x
__device__ float    g_thr[20];               // per-channel BN mean (threshold)
__device__ unsigned g_wp2p[50 * 5 * 8];      // conv2 masks, 8-word padded rows
__device__ unsigned g_wz2[50 * 25];          // conv2 W==0 masks
__device__ int      g_zflag2;                // any zero conv2 weight
__device__ unsigned g_wpl[500 * 40];         // linear sign(W)>0 masks (1250 bits)
__device__ unsigned g_wzl[500 * 40];         // linear W==0 masks
__device__ int      g_zflagl;
__device__ float    g_alphal[500];           // linear alpha = mean(|W|, dim=1)
__device__ unsigned g_Bp[N_IMG * 40];        // sign(+1) bit-plane into linear
__device__ unsigned g_Bn[N_IMG * 40];        // sign(-1) bit-plane into linear

// ---------------- K_pre: batch-sum of x per pixel -------------------------
__global__ __launch_bounds__(256) void k_pre(const float* __restrict__ x) {
    int b = blockIdx.x, t = threadIdx.x;
    const float* base = x + (size_t)b * 64 * 1024 + t * 4;
    float4 acc = make_float4(0.f, 0.f, 0.f, 0.f);
    for (int i = 0; i < 64; ++i) {
        float4 v = *(const float4*)(base + (size_t)i * 1024);
        acc.x += v.x; acc.y += v.y; acc.z += v.z; acc.w += v.w;
    }
    *(float4*)(g_Ppart + b * 1024 + t * 4) = acc;
}

// ---------------- K_thr: thresholds (b0) + weight masks (b1-4) + alpha ----
__global__ __launch_bounds__(1024) void k_thr(const float* __restrict__ w1,
                                              const float* __restrict__ w2,
                                              const float* __restrict__ wl) {
    int b = blockIdx.x, t = threadIdx.x;
    if (b == 0) {
        __shared__ double Ps[1024];
        __shared__ double Ts[25];
        double s0 = 0.0, s1 = 0.0;
        for (int i = 0; i < 128; i += 2) {
            s0 += (double)g_Ppart[i * 1024 + t];
            s1 += (double)g_Ppart[(i + 1) * 1024 + t];
        }
        Ps[t] = s0 + s1;
        __syncthreads();
        if (t < 800) {                // 25 taps x 32 lanes, fixed shfl tree
            int g = t >> 5, lane = t & 31;
            int dy = g / 5, dx = g % 5;
            double a = 0.0;
            for (int idx = lane; idx < 784; idx += 32) {
                int i = idx / 28, j = idx % 28;
                a += Ps[(i + dy) * 32 + (j + dx)];
            }
#pragma unroll
            for (int o = 16; o; o >>= 1) a += __shfl_down_sync(0xffffffffu, a, o);
            if (lane == 0) Ts[g] = a;
        }
        __syncthreads();
        if (t < 20) {
            double d = 0.0;
            for (int k = 0; k < 25; ++k) d += (double)w1[t * 25 + k] * Ts[k];
            g_thr[t] = (float)(d / (8192.0 * 28.0 * 28.0));
        }
    } else if (b < 5) {
        int gid = (b - 1) * 1024 + t;            // 0..4095
        if (gid < 1250) {                         // conv2 masks
            int oc = gid / 25, d = gid % 25;
            int dy = d / 5, dx = d % 5;
            unsigned mp = 0, mz = 0;
            for (int c = 0; c < 20; ++c) {
                float w = w2[oc * 500 + c * 25 + d];
                if (w > 0.f) mp |= 1u << c;
                else if (w == 0.f) mz |= 1u << c;
            }
            g_wz2[gid] = mz;
            g_wp2p[(oc * 5 + dy) * 8 + dx] = mp;
            if (dx == 0) {                        // zero the pad words
                g_wp2p[(oc * 5 + dy) * 8 + 5] = 0;
                g_wp2p[(oc * 5 + dy) * 8 + 6] = 0;
                g_wp2p[(oc * 5 + dy) * 8 + 7] = 0;
            }
            if (mz) atomicOr(&g_zflag2, 1);
        }
        for (int e = gid; e < 500 * 40; e += 4096) {  // linear masks
            int j = e / 40, wi = e % 40;
            unsigned mp = 0, mz = 0;
            for (int bit = 0; bit < 32; ++bit) {
                int i = wi * 32 + bit;
                if (i < 1250) {
                    float w = wl[j * 1250 + i];
                    if (w > 0.f) mp |= 1u << bit;
                    else if (w == 0.f) mz |= 1u << bit;
                }
            }
            g_wpl[e] = mp; g_wzl[e] = mz;
            if (mz) atomicOr(&g_zflagl, 1);
        }
    } else {
        int w = (b - 5) * 32 + (t >> 5);         // alpha_l row index, 16 blocks
        int lane = t & 31;
        if (w < 500) {
            double s = 0.0;
            for (int i = lane; i < 1250; i += 32)
                s += fabs((double)wl[w * 1250 + i]);
#pragma unroll
            for (int o = 16; o; o >>= 1) s += __shfl_down_sync(0xffffffffu, s, o);
            if (lane == 0) g_alphal[w] = (float)(s / 1250.0);
        }
    }
}

// ---------------- K_conv: fused conv1 + conv2 per 2 images ----------------
#define ROWW 20                       // padded row width (words)
__global__ __launch_bounds__(256) void k_conv(const float* __restrict__ x,
                                              const float* __restrict__ w1) {
    __shared__ __align__(16) float xs[1024];
    __shared__ __align__(16) float ws[20 * 40];   // 8-float padded rows
    __shared__ float thr_s[20];
    __shared__ unsigned b1s[2][196];
    __shared__ __align__(16) unsigned BsA[2 * 14 * ROWW];
    __shared__ __align__(16) unsigned BsB[2 * 14 * ROWW];
    __shared__ int PB[2][100];
    __shared__ __align__(16) unsigned Wps[50 * 5 * 8];
    __shared__ __align__(16) unsigned char sPN[2][1280];
    int n0 = blockIdx.x * 2, t = threadIdx.x;

    // --- stage conv1 weights (padded), thresholds, conv2 masks ---
    for (int i = t; i < 500; i += 256) {
        int c = i / 25, k = i % 25;
        ws[c * 40 + (k / 5) * 8 + (k % 5)] = w1[i];
    }
    if (t < 20) thr_s[t] = g_thr[t];
    for (int i = t; i < 2000; i += 256) Wps[i] = g_wp2p[i];
    if (t < 60) sPN[t / 30][1250 + (t % 30)] = 0;

    // --- phase 1: conv1 + threshold + pool + bit-pack, 2 images ---
#pragma unroll 1
    for (int img = 0; img < 2; ++img) {
        __syncthreads();              // weights ready / prev img done with xs
        for (int i = t; i < 1024; i += 256) xs[i] = x[(size_t)(n0 + img) * 1024 + i];
        __syncthreads();
        if (t < 196) {
            int py = t / 14, px = t % 14;
            float xp[6][6];
            const float* xb = &xs[(py * 2) * 32 + px * 2];
#pragma unroll
            for (int r = 0; r < 6; ++r) {
#pragma unroll
                for (int c2 = 0; c2 < 3; ++c2) {
                    float2 v = *(const float2*)(xb + r * 32 + c2 * 2);
                    xp[r][c2 * 2] = v.x; xp[r][c2 * 2 + 1] = v.y;
                }
            }
            unsigned word = 0;
#pragma unroll 1
            for (int c = 0; c < 20; ++c) {
                const float* wc = &ws[c * 40];
                float a0 = 0.f, a1 = 0.f, a2 = 0.f, a3 = 0.f;
#pragma unroll
                for (int dy = 0; dy < 5; ++dy) {
                    float4 wq = *(const float4*)(wc + dy * 8);
                    float w4 = wc[dy * 8 + 4];
                    float wv[5] = {wq.x, wq.y, wq.z, wq.w, w4};
#pragma unroll
                    for (int dx = 0; dx < 5; ++dx) {
                        float w = wv[dx];
                        a0 = fmaf(w, xp[dy][dx],         a0);
                        a1 = fmaf(w, xp[dy][dx + 1],     a1);
                        a2 = fmaf(w, xp[dy + 1][dx],     a2);
                        a3 = fmaf(w, xp[dy + 1][dx + 1], a3);
                    }
                }
                float m = fmaxf(fmaxf(a0, a1), fmaxf(a2, a3));
                if (m > thr_s[c]) word |= (1u << c);
            }
            b1s[img][t] = word;
        }
    }
    __syncthreads();

    // --- phase 2: XNOR conv2 on smem-resident bits (R8 layout) ---
    for (int i = t; i < 2 * 196; i += 256) {
        int img = i / 196, p = i % 196;
        int y = p / 14, xx = p % 14;
        unsigned bv = b1s[img][p];
        BsA[img * 14 * ROWW + y * ROWW + xx] = bv;
        if (xx >= 2) BsB[img * 14 * ROWW + y * ROWW + xx - 2] = bv;
    }
    __syncthreads();
    for (int i = t; i < 2 * 100; i += 256) {
        int img = i / 100, p = i % 100;
        int y = p / 10, xx = p % 10;
        const unsigned* B = &BsA[img * 14 * ROWW];
        int s = 0;
#pragma unroll
        for (int dy = 0; dy < 5; ++dy)
#pragma unroll
            for (int dx = 0; dx < 5; ++dx)
                s += __popc(B[(y + dy) * ROWW + xx + dx]);
        PB[img][p] = s;
    }
    __syncthreads();
    int zf = g_zflag2;
    if (t < 250) {
        int oc = t / 5, cx = t % 5;
        int odd = cx & 1;
        const unsigned* P0 = odd ? BsB : BsA;
        int colbase = odd ? (2 * cx - 2) : (2 * cx);
        unsigned W[25];
#pragma unroll
        for (int j = 0; j < 5; ++j) {
            uint4 wq = *(const uint4*)(&Wps[oc * 40 + j * 8]);
            W[j * 5] = wq.x; W[j * 5 + 1] = wq.y; W[j * 5 + 2] = wq.z; W[j * 5 + 3] = wq.w;
            W[j * 5 + 4] = Wps[oc * 40 + j * 8 + 4];
        }
#pragma unroll 1
        for (int r = 0; r < 5; ++r) {
#pragma unroll 1
            for (int img = 0; img < 2; ++img) {
                const unsigned* bp0 = P0 + img * 14 * ROWW + (2 * r) * ROWW + colbase;
                int a00 = 0, a01 = 0, a10 = 0, a11 = 0;
#pragma unroll
                for (int rr = 0; rr < 6; ++rr) {
                    const unsigned* bp = bp0 + rr * ROWW;
                    uint4 q = *(const uint4*)bp;
                    uint2 d2 = *(const uint2*)(bp + 4);
                    unsigned p0 = q.x, p1 = q.y, p2 = q.z, p3 = q.w, p4 = d2.x, p5 = d2.y;
                    if (rr < 5) {
                        a00 += __popc(p0 & W[rr * 5]) + __popc(p1 & W[rr * 5 + 1])
                             + __popc(p2 & W[rr * 5 + 2]) + __popc(p3 & W[rr * 5 + 3])
                             + __popc(p4 & W[rr * 5 + 4]);
                        a01 += __popc(p1 & W[rr * 5]) + __popc(p2 & W[rr * 5 + 1])
                             + __popc(p3 & W[rr * 5 + 2]) + __popc(p4 & W[rr * 5 + 3])
                             + __popc(p5 & W[rr * 5 + 4]);
                    }
                    if (rr >= 1) {
                        a10 += __popc(p0 & W[(rr - 1) * 5]) + __popc(p1 & W[(rr - 1) * 5 + 1])
                             + __popc(p2 & W[(rr - 1) * 5 + 2]) + __popc(p3 & W[(rr - 1) * 5 + 3])
                             + __popc(p4 & W[(rr - 1) * 5 + 4]);
                        a11 += __popc(p1 & W[(rr - 1) * 5]) + __popc(p2 & W[(rr - 1) * 5 + 1])
                             + __popc(p3 & W[(rr - 1) * 5 + 2]) + __popc(p4 & W[(rr - 1) * 5 + 3])
                             + __popc(p5 & W[(rr - 1) * 5 + 4]);
                    }
                }
                int v00 = 2 * a00 - PB[img][(2 * r) * 10 + 2 * cx];
                int v01 = 2 * a01 - PB[img][(2 * r) * 10 + 2 * cx + 1];
                int v10 = 2 * a10 - PB[img][(2 * r + 1) * 10 + 2 * cx];
                int v11 = 2 * a11 - PB[img][(2 * r + 1) * 10 + 2 * cx + 1];
                if (zf) {  // uniform, never taken with this dataset
                    const unsigned* B = &BsA[img * 14 * ROWW + (2 * r) * ROWW + 2 * cx];
                    int z00 = 0, z01 = 0, z10 = 0, z11 = 0;
                    for (int dy = 0; dy < 5; ++dy)
                        for (int dx = 0; dx < 5; ++dx) {
                            unsigned wz = g_wz2[oc * 25 + dy * 5 + dx];
                            z00 += __popc(B[dy * ROWW + dx] & wz);
                            z01 += __popc(B[dy * ROWW + dx + 1] & wz);
                            z10 += __popc(B[(dy + 1) * ROWW + dx] & wz);
                            z11 += __popc(B[(dy + 1) * ROWW + dx + 1] & wz);
                        }
                    v00 += z00; v01 += z01; v10 += z10; v11 += z11;
                }
                int best = max(max(v00, v01), max(v10, v11));
                sPN[img][oc * 25 + r * 5 + cx] =
                    (unsigned char)((best > 0 ? 1 : 0) | (best < 0 ? 2 : 0));
            }
        }
    }
    __syncthreads();
    if (t < 2 * 40) {                    // byte planes -> bit planes
        int img = t / 40, wi = t % 40;
        const unsigned* src = (const unsigned*)&sPN[img][0] + wi * 8;
        unsigned P = 0, N = 0;
#pragma unroll
        for (int j = 0; j < 8; ++j) {
            unsigned b = src[j];
            P |= ((((b & 0x01010101u) * 0x00204081u) >> 21) & 0xFu) << (4 * j);
            N |= (((((b >> 1) & 0x01010101u) * 0x00204081u) >> 21) & 0xFu) << (4 * j);
        }
        g_Bp[(size_t)(n0 + img) * 40 + wi] = P;
        g_Bn[(size_t)(n0 + img) * 40 + wi] = N;
    }
}

// ---------------- K4: binary linear (XNOR-LOP3) + clip + fc, 16 imgs ------
#define D_IMGS 16
__global__ __launch_bounds__(512) void k_dense(const float* __restrict__ fcw,
                                               const float* __restrict__ fcb,
                                               float* __restrict__ out) {
    extern __shared__ unsigned sm[];
    unsigned* Ws  = sm;                       // 500*41 (padded, conflict-free)
    unsigned* Bps = Ws + 500 * 41;            // D*40  sign bit-plane (+1)
    unsigned* Bns = Bps + D_IMGS * 40;        // D*40  sign bit-plane (-1), zf path only
    unsigned* Us  = Bns + D_IMGS * 40;        // D*40  nonzero mask = Bp|Bn
    int*      pcU = (int*)(Us + D_IMGS * 40); // D
    float*    hs  = (float*)(pcU + D_IMGS);   // D*500
    int t = threadIdx.x;
    int n0 = blockIdx.x * D_IMGS;
    for (int i = t; i < 500 * 40; i += 512) Ws[(i / 40) * 41 + (i % 40)] = g_wpl[i];
    for (int i = t; i < D_IMGS * 40; i += 512) {
        int img = i / 40, wi = i % 40;
        unsigned bp = g_Bp[(size_t)(n0 + img) * 40 + wi];
        unsigned bn = g_Bn[(size_t)(n0 + img) * 40 + wi];
        Bps[img * 40 + wi] = bp;
        Bns[img * 40 + wi] = bn;
        Us[img * 40 + wi]  = bp | bn;
    }
    __syncthreads();
    if (t < D_IMGS) {
        int s = 0;
        for (int k = 0; k < 40; ++k) s += __popc(Us[t * 40 + k]);
        pcU[t] = s;
    }
    __syncthreads();
    int zf = g_zflagl;
    for (int j = t; j < 500; j += 512) {
        unsigned wr[40];
#pragma unroll
        for (int k = 0; k < 40; ++k) wr[k] = Ws[j * 41 + k];
        float al = g_alphal[j];
#pragma unroll 1
        for (int img = 0; img < D_IMGS; ++img) {
            int m = 0;
#pragma unroll
            for (int k = 0; k < 40; ++k) {
                m += __popc((~(Bps[img * 40 + k] ^ wr[k])) & Us[img * 40 + k]);
            }
            int vi = 2 * m - pcU[img];
            if (zf) {  // uniform, never taken with this dataset
                int cp = 0, cn = 0;
                for (int k = 0; k < 40; ++k) {
                    unsigned z = g_wzl[j * 40 + k];
                    cp += __popc(Bps[img * 40 + k] & z);
                    cn += __popc(Bns[img * 40 + k] & z);
                }
                vi += cp - cn;
            }
            float h = fminf(fmaxf((float)vi * al, -1.f), 1.f);
            hs[img * 500 + j] = h;
        }
    }
    __syncthreads();
    int w = t >> 5, lane = t & 31;   // warp w -> image w
    for (int lg = 0; lg < 10; ++lg) {
        float p = 0.f;
        for (int j = lane; j < 500; j += 32)
            p += hs[w * 500 + j] * __ldg(&fcw[lg * 500 + j]);
#pragma unroll
        for (int o = 16; o; o >>= 1) p += __shfl_down_sync(0xffffffffu, p, o);
        if (lane == 0) out[(size_t)(n0 + w) * 10 + lg] = p + fcb[lg];
    }
}

// ---------------- launch ---------------------------------------------------
extern "C" void kernel_launch(void* const* d_in, const int* in_sizes, int n_in,
                              void* d_out, int out_size) {
    const float* x   = (const float*)d_in[0];
    const float* w1  = (const float*)d_in[1];
    const float* w2  = (const float*)d_in[2];
    const float* wl  = (const float*)d_in[3];
    const float* fcw = (const float*)d_in[4];
    const float* fcb = (const float*)d_in[5];
    float* out = (float*)d_out;

    size_t dense_smem = (500 * 41 + D_IMGS * 40 * 3 + D_IMGS) * 4 + D_IMGS * 500 * 4;
    cudaFuncSetAttribute(k_dense, cudaFuncAttributeMaxDynamicSharedMemorySize,
                         (int)dense_smem);

    k_pre<<<128, 256>>>(x);
    k_thr<<<21, 1024>>>(w1, w2, wl);
    k_conv<<<N_IMG / 2, 256>>>(x, w1);
    k_dense<<<N_IMG / D_IMGS, 512, dense_smem>>>(fcw, fcb, out);
}

// round 13
// speedup vs baseline: 1.8453x; 1.0310x over previous
#include <cuda_runtime.h>
#include <cstdint>

#define N_IMG 8192

// ---------------- scratch (device globals; no allocations) ----------------
__device__ float    g_Ppart[128 * 1024];     // partial batch sums of x
__device__ float    g_thr[20];               // per-channel BN mean (threshold)
__device__ unsigned g_wp2p[50 * 5 * 8];      // conv2 masks, 8-word padded rows
__device__ unsigned g_wz2[50 * 25];          // conv2 W==0 masks
__device__ int      g_zflag2;                // any zero conv2 weight
__device__ __align__(16) unsigned g_wpl[500 * 40];  // linear sign(W)>0 masks
__device__ unsigned g_wzl[500 * 40];         // linear W==0 masks
__device__ int      g_zflagl;
__device__ float    g_alphal[500];           // linear alpha = mean(|W|, dim=1)
__device__ unsigned g_Bp[N_IMG * 40];        // sign(+1) bit-plane into linear
__device__ unsigned g_Bn[N_IMG * 40];        // sign(-1) bit-plane into linear

// ---------------- K_pre: batch-sum of x per pixel -------------------------
__global__ __launch_bounds__(256) void k_pre(const float* __restrict__ x) {
    int b = blockIdx.x, t = threadIdx.x;
    const float* base = x + (size_t)b * 64 * 1024 + t * 4;
    float4 acc = make_float4(0.f, 0.f, 0.f, 0.f);
    for (int i = 0; i < 64; ++i) {
        float4 v = *(const float4*)(base + (size_t)i * 1024);
        acc.x += v.x; acc.y += v.y; acc.z += v.z; acc.w += v.w;
    }
    *(float4*)(g_Ppart + b * 1024 + t * 4) = acc;
}

// ---------------- K_thr: thresholds (b0) + weight masks (b1-4) + alpha ----
__global__ __launch_bounds__(1024) void k_thr(const float* __restrict__ w1,
                                              const float* __restrict__ w2,
                                              const float* __restrict__ wl) {
    int b = blockIdx.x, t = threadIdx.x;
    if (b == 0) {
        __shared__ double Ps[1024];
        __shared__ double Ts[25];
        double s0 = 0.0, s1 = 0.0;
        for (int i = 0; i < 128; i += 2) {
            s0 += (double)g_Ppart[i * 1024 + t];
            s1 += (double)g_Ppart[(i + 1) * 1024 + t];
        }
        Ps[t] = s0 + s1;
        __syncthreads();
        if (t < 800) {                // 25 taps x 32 lanes, fixed shfl tree
            int g = t >> 5, lane = t & 31;
            int dy = g / 5, dx = g % 5;
            double a = 0.0;
            for (int idx = lane; idx < 784; idx += 32) {
                int i = idx / 28, j = idx % 28;
                a += Ps[(i + dy) * 32 + (j + dx)];
            }
#pragma unroll
            for (int o = 16; o; o >>= 1) a += __shfl_down_sync(0xffffffffu, a, o);
            if (lane == 0) Ts[g] = a;
        }
        __syncthreads();
        if (t < 20) {
            double d = 0.0;
            for (int k = 0; k < 25; ++k) d += (double)w1[t * 25 + k] * Ts[k];
            g_thr[t] = (float)(d / (8192.0 * 28.0 * 28.0));
        }
    } else if (b < 5) {
        int gid = (b - 1) * 1024 + t;            // 0..4095
        if (gid < 1250) {                         // conv2 masks
            int oc = gid / 25, d = gid % 25;
            int dy = d / 5, dx = d % 5;
            unsigned mp = 0, mz = 0;
            for (int c = 0; c < 20; ++c) {
                float w = w2[oc * 500 + c * 25 + d];
                if (w > 0.f) mp |= 1u << c;
                else if (w == 0.f) mz |= 1u << c;
            }
            g_wz2[gid] = mz;
            g_wp2p[(oc * 5 + dy) * 8 + dx] = mp;
            if (dx == 0) {                        // zero the pad words
                g_wp2p[(oc * 5 + dy) * 8 + 5] = 0;
                g_wp2p[(oc * 5 + dy) * 8 + 6] = 0;
                g_wp2p[(oc * 5 + dy) * 8 + 7] = 0;
            }
            if (mz) atomicOr(&g_zflag2, 1);
        }
        for (int e = gid; e < 500 * 40; e += 4096) {  // linear masks
            int j = e / 40, wi = e % 40;
            unsigned mp = 0, mz = 0;
            for (int bit = 0; bit < 32; ++bit) {
                int i = wi * 32 + bit;
                if (i < 1250) {
                    float w = wl[j * 1250 + i];
                    if (w > 0.f) mp |= 1u << bit;
                    else if (w == 0.f) mz |= 1u << bit;
                }
            }
            g_wpl[e] = mp; g_wzl[e] = mz;
            if (mz) atomicOr(&g_zflagl, 1);
        }
    } else {
        int w = (b - 5) * 32 + (t >> 5);         // alpha_l row index, 16 blocks
        int lane = t & 31;
        if (w < 500) {
            double s = 0.0;
            for (int i = lane; i < 1250; i += 32)
                s += fabs((double)wl[w * 1250 + i]);
#pragma unroll
            for (int o = 16; o; o >>= 1) s += __shfl_down_sync(0xffffffffu, s, o);
            if (lane == 0) g_alphal[w] = (float)(s / 1250.0);
        }
    }
}

// ---------------- K_conv: fused conv1 + conv2 per 2 images ----------------
#define ROWW 20                       // padded row width (words)
__global__ __launch_bounds__(256) void k_conv(const float* __restrict__ x,
                                              const float* __restrict__ w1) {
    __shared__ __align__(16) float xs[1024];
    __shared__ __align__(16) float ws[20 * 40];   // 8-float padded rows
    __shared__ float thr_s[20];
    __shared__ unsigned b1s[2][196];
    __shared__ __align__(16) unsigned BsA[2 * 14 * ROWW];
    __shared__ __align__(16) unsigned BsB[2 * 14 * ROWW];
    __shared__ int PB[2][100];
    __shared__ __align__(16) unsigned Wps[50 * 5 * 8];
    __shared__ __align__(16) unsigned char sPN[2][1280];
    int n0 = blockIdx.x * 2, t = threadIdx.x;

    // --- stage conv1 weights (padded), thresholds, conv2 masks ---
    for (int i = t; i < 500; i += 256) {
        int c = i / 25, k = i % 25;
        ws[c * 40 + (k / 5) * 8 + (k % 5)] = w1[i];
    }
    if (t < 20) thr_s[t] = g_thr[t];
    for (int i = t; i < 2000; i += 256) Wps[i] = g_wp2p[i];
    if (t < 60) sPN[t / 30][1250 + (t % 30)] = 0;

    // --- phase 1: conv1 + threshold + pool + bit-pack, 2 images ---
#pragma unroll 1
    for (int img = 0; img < 2; ++img) {
        __syncthreads();              // weights ready / prev img done with xs
        for (int i = t; i < 1024; i += 256) xs[i] = x[(size_t)(n0 + img) * 1024 + i];
        __syncthreads();
        if (t < 196) {
            int py = t / 14, px = t % 14;
            float xp[6][6];
            const float* xb = &xs[(py * 2) * 32 + px * 2];
#pragma unroll
            for (int r = 0; r < 6; ++r) {
#pragma unroll
                for (int c2 = 0; c2 < 3; ++c2) {
                    float2 v = *(const float2*)(xb + r * 32 + c2 * 2);
                    xp[r][c2 * 2] = v.x; xp[r][c2 * 2 + 1] = v.y;
                }
            }
            unsigned word = 0;
#pragma unroll 1
            for (int c = 0; c < 20; ++c) {
                const float* wc = &ws[c * 40];
                float a0 = 0.f, a1 = 0.f, a2 = 0.f, a3 = 0.f;
#pragma unroll
                for (int dy = 0; dy < 5; ++dy) {
                    float4 wq = *(const float4*)(wc + dy * 8);
                    float w4 = wc[dy * 8 + 4];
                    float wv[5] = {wq.x, wq.y, wq.z, wq.w, w4};
#pragma unroll
                    for (int dx = 0; dx < 5; ++dx) {
                        float w = wv[dx];
                        a0 = fmaf(w, xp[dy][dx],         a0);
                        a1 = fmaf(w, xp[dy][dx + 1],     a1);
                        a2 = fmaf(w, xp[dy + 1][dx],     a2);
                        a3 = fmaf(w, xp[dy + 1][dx + 1], a3);
                    }
                }
                float m = fmaxf(fmaxf(a0, a1), fmaxf(a2, a3));
                if (m > thr_s[c]) word |= (1u << c);
            }
            b1s[img][t] = word;
        }
    }
    __syncthreads();

    // --- phase 2: XNOR conv2 on smem-resident bits (R8 layout) ---
    for (int i = t; i < 2 * 196; i += 256) {
        int img = i / 196, p = i % 196;
        int y = p / 14, xx = p % 14;
        unsigned bv = b1s[img][p];
        BsA[img * 14 * ROWW + y * ROWW + xx] = bv;
        if (xx >= 2) BsB[img * 14 * ROWW + y * ROWW + xx - 2] = bv;
    }
    __syncthreads();
    for (int i = t; i < 2 * 100; i += 256) {
        int img = i / 100, p = i % 100;
        int y = p / 10, xx = p % 10;
        const unsigned* B = &BsA[img * 14 * ROWW];
        int s = 0;
#pragma unroll
        for (int dy = 0; dy < 5; ++dy)
#pragma unroll
            for (int dx = 0; dx < 5; ++dx)
                s += __popc(B[(y + dy) * ROWW + xx + dx]);
        PB[img][p] = s;
    }
    __syncthreads();
    int zf = g_zflag2;
    if (t < 250) {
        int oc = t / 5, cx = t % 5;
        int odd = cx & 1;
        const unsigned* P0 = odd ? BsB : BsA;
        int colbase = odd ? (2 * cx - 2) : (2 * cx);
        unsigned W[25];
#pragma unroll
        for (int j = 0; j < 5; ++j) {
            uint4 wq = *(const uint4*)(&Wps[oc * 40 + j * 8]);
            W[j * 5] = wq.x; W[j * 5 + 1] = wq.y; W[j * 5 + 2] = wq.z; W[j * 5 + 3] = wq.w;
            W[j * 5 + 4] = Wps[oc * 40 + j * 8 + 4];
        }
#pragma unroll 1
        for (int r = 0; r < 5; ++r) {
#pragma unroll 1
            for (int img = 0; img < 2; ++img) {
                const unsigned* bp0 = P0 + img * 14 * ROWW + (2 * r) * ROWW + colbase;
                int a00 = 0, a01 = 0, a10 = 0, a11 = 0;
#pragma unroll
                for (int rr = 0; rr < 6; ++rr) {
                    const unsigned* bp = bp0 + rr * ROWW;
                    uint4 q = *(const uint4*)bp;
                    uint2 d2 = *(const uint2*)(bp + 4);
                    unsigned p0 = q.x, p1 = q.y, p2 = q.z, p3 = q.w, p4 = d2.x, p5 = d2.y;
                    if (rr < 5) {
                        a00 += __popc(p0 & W[rr * 5]) + __popc(p1 & W[rr * 5 + 1])
                             + __popc(p2 & W[rr * 5 + 2]) + __popc(p3 & W[rr * 5 + 3])
                             + __popc(p4 & W[rr * 5 + 4]);
                        a01 += __popc(p1 & W[rr * 5]) + __popc(p2 & W[rr * 5 + 1])
                             + __popc(p3 & W[rr * 5 + 2]) + __popc(p4 & W[rr * 5 + 3])
                             + __popc(p5 & W[rr * 5 + 4]);
                    }
                    if (rr >= 1) {
                        a10 += __popc(p0 & W[(rr - 1) * 5]) + __popc(p1 & W[(rr - 1) * 5 + 1])
                             + __popc(p2 & W[(rr - 1) * 5 + 2]) + __popc(p3 & W[(rr - 1) * 5 + 3])
                             + __popc(p4 & W[(rr - 1) * 5 + 4]);
                        a11 += __popc(p1 & W[(rr - 1) * 5]) + __popc(p2 & W[(rr - 1) * 5 + 1])
                             + __popc(p3 & W[(rr - 1) * 5 + 2]) + __popc(p4 & W[(rr - 1) * 5 + 3])
                             + __popc(p5 & W[(rr - 1) * 5 + 4]);
                    }
                }
                int v00 = 2 * a00 - PB[img][(2 * r) * 10 + 2 * cx];
                int v01 = 2 * a01 - PB[img][(2 * r) * 10 + 2 * cx + 1];
                int v10 = 2 * a10 - PB[img][(2 * r + 1) * 10 + 2 * cx];
                int v11 = 2 * a11 - PB[img][(2 * r + 1) * 10 + 2 * cx + 1];
                if (zf) {  // uniform, never taken with this dataset
                    const unsigned* B = &BsA[img * 14 * ROWW + (2 * r) * ROWW + 2 * cx];
                    int z00 = 0, z01 = 0, z10 = 0, z11 = 0;
                    for (int dy = 0; dy < 5; ++dy)
                        for (int dx = 0; dx < 5; ++dx) {
                            unsigned wz = g_wz2[oc * 25 + dy * 5 + dx];
                            z00 += __popc(B[dy * ROWW + dx] & wz);
                            z01 += __popc(B[dy * ROWW + dx + 1] & wz);
                            z10 += __popc(B[(dy + 1) * ROWW + dx] & wz);
                            z11 += __popc(B[(dy + 1) * ROWW + dx + 1] & wz);
                        }
                    v00 += z00; v01 += z01; v10 += z10; v11 += z11;
                }
                int best = max(max(v00, v01), max(v10, v11));
                sPN[img][oc * 25 + r * 5 + cx] =
                    (unsigned char)((best > 0 ? 1 : 0) | (best < 0 ? 2 : 0));
            }
        }
    }
    __syncthreads();
    if (t < 2 * 40) {                    // byte planes -> bit planes
        int img = t / 40, wi = t % 40;
        const unsigned* src = (const unsigned*)&sPN[img][0] + wi * 8;
        unsigned P = 0, N = 0;
#pragma unroll
        for (int j = 0; j < 8; ++j) {
            unsigned b = src[j];
            P |= ((((b & 0x01010101u) * 0x00204081u) >> 21) & 0xFu) << (4 * j);
            N |= (((((b >> 1) & 0x01010101u) * 0x00204081u) >> 21) & 0xFu) << (4 * j);
        }
        g_Bp[(size_t)(n0 + img) * 40 + wi] = P;
        g_Bn[(size_t)(n0 + img) * 40 + wi] = N;
    }
}

// ---------------- K4: binary linear + clip + fc — W streamed from gmem ----
#define D_IMGS 16
__global__ __launch_bounds__(512, 2) void k_dense(const float* __restrict__ fcw,
                                                  const float* __restrict__ fcb,
                                                  float* __restrict__ out) {
    __shared__ __align__(16) unsigned Bps[D_IMGS * 40];
    __shared__ __align__(16) unsigned Bns[D_IMGS * 40];
    __shared__ __align__(16) unsigned Us[D_IMGS * 40];
    __shared__ int pcU[D_IMGS];
    __shared__ float hs[D_IMGS * 500];
    int t = threadIdx.x;
    int n0 = blockIdx.x * D_IMGS;
    for (int i = t; i < D_IMGS * 40; i += 512) {
        int img = i / 40, wi = i % 40;
        unsigned bp = g_Bp[(size_t)(n0 + img) * 40 + wi];
        unsigned bn = g_Bn[(size_t)(n0 + img) * 40 + wi];
        Bps[img * 40 + wi] = bp;
        Bns[img * 40 + wi] = bn;
        Us[img * 40 + wi]  = bp | bn;
    }
    __syncthreads();
    if (t < D_IMGS) {
        int s = 0;
        for (int k = 0; k < 40; ++k) s += __popc(Us[t * 40 + k]);
        pcU[t] = s;
    }
    __syncthreads();
    int zf = g_zflagl;
    for (int j = t; j < 500; j += 512) {
        float al = g_alphal[j];
        int m[D_IMGS];
#pragma unroll
        for (int img = 0; img < D_IMGS; ++img) m[img] = 0;
#pragma unroll 1
        for (int half = 0; half < 2; ++half) {
            unsigned wr[20];
#pragma unroll
            for (int k = 0; k < 5; ++k) {
                uint4 q = *(const uint4*)(&g_wpl[j * 40 + half * 20 + k * 4]);
                wr[k * 4] = q.x; wr[k * 4 + 1] = q.y;
                wr[k * 4 + 2] = q.z; wr[k * 4 + 3] = q.w;
            }
#pragma unroll
            for (int img = 0; img < D_IMGS; ++img) {
                const unsigned* Bb = &Bps[img * 40 + half * 20];
                const unsigned* Ub = &Us[img * 40 + half * 20];
                int mm = 0;
#pragma unroll
                for (int k = 0; k < 5; ++k) {
                    uint4 bq = *(const uint4*)(Bb + k * 4);
                    uint4 uq = *(const uint4*)(Ub + k * 4);
                    mm += __popc((~(bq.x ^ wr[k * 4]))     & uq.x);
                    mm += __popc((~(bq.y ^ wr[k * 4 + 1])) & uq.y);
                    mm += __popc((~(bq.z ^ wr[k * 4 + 2])) & uq.z);
                    mm += __popc((~(bq.w ^ wr[k * 4 + 3])) & uq.w);
                }
                m[img] += mm;
            }
        }
#pragma unroll
        for (int img = 0; img < D_IMGS; ++img) {
            int vi = 2 * m[img] - pcU[img];
            if (zf) {  // uniform, never taken with this dataset
                int cp = 0, cn = 0;
                for (int k = 0; k < 40; ++k) {
                    unsigned z = g_wzl[j * 40 + k];
                    cp += __popc(Bps[img * 40 + k] & z);
                    cn += __popc(Bns[img * 40 + k] & z);
                }
                vi += cp - cn;
            }
            float h = fminf(fmaxf((float)vi * al, -1.f), 1.f);
            hs[img * 500 + j] = h;
        }
    }
    __syncthreads();
    int w = t >> 5, lane = t & 31;   // warp w -> image w
    for (int lg = 0; lg < 10; ++lg) {
        float p = 0.f;
        for (int j = lane; j < 500; j += 32)
            p += hs[w * 500 + j] * __ldg(&fcw[lg * 500 + j]);
#pragma unroll
        for (int o = 16; o; o >>= 1) p += __shfl_down_sync(0xffffffffu, p, o);
        if (lane == 0) out[(size_t)(n0 + w) * 10 + lg] = p + fcb[lg];
    }
}

// ---------------- launch ---------------------------------------------------
extern "C" void kernel_launch(void* const* d_in, const int* in_sizes, int n_in,
                              void* d_out, int out_size) {
    const float* x   = (const float*)d_in[0];
    const float* w1  = (const float*)d_in[1];
    const float* w2  = (const float*)d_in[2];
    const float* wl  = (const float*)d_in[3];
    const float* fcw = (const float*)d_in[4];
    const float* fcb = (const float*)d_in[5];
    float* out = (float*)d_out;

    k_pre<<<128, 256>>>(x);
    k_thr<<<21, 1024>>>(w1, w2, wl);
    k_conv<<<N_IMG / 2, 256>>>(x, w1);
    k_dense<<<N_IMG / D_IMGS, 512>>>(fcw, fcb, out);
}

// round 14
// speedup vs baseline: 1.9280x; 1.0448x over previous
#include <cuda_runtime.h>
#include <cstdint>

#define N_IMG 8192

// ---------------- scratch (device globals; no allocations) ----------------
__device__ float    g_Ppart[128 * 1024];     // partial batch sums of x
__device__ float    g_thr[20];               // per-channel BN mean (threshold)
__device__ unsigned g_wp2p[50 * 5 * 8];      // conv2 masks, 8-word padded rows
__device__ unsigned g_wz2[50 * 25];          // conv2 W==0 masks
__device__ int      g_zflag2;                // any zero conv2 weight
__device__ __align__(16) unsigned g_wpl[500 * 40];  // linear sign(W)>0 masks
__device__ unsigned g_wzl[500 * 40];         // linear W==0 masks
__device__ int      g_zflagl;
__device__ float    g_alphal[500];           // linear alpha = mean(|W|, dim=1)
__device__ unsigned g_Bp[N_IMG * 40];        // sign(+1) bit-plane into linear
__device__ unsigned g_Bn[N_IMG * 40];        // sign(-1) bit-plane into linear

// ---------------- K_pre: batch-sum of x per pixel -------------------------
__global__ __launch_bounds__(256) void k_pre(const float* __restrict__ x) {
    int b = blockIdx.x, t = threadIdx.x;
    const float* base = x + (size_t)b * 64 * 1024 + t * 4;
    float4 acc = make_float4(0.f, 0.f, 0.f, 0.f);
    for (int i = 0; i < 64; ++i) {
        float4 v = *(const float4*)(base + (size_t)i * 1024);
        acc.x += v.x; acc.y += v.y; acc.z += v.z; acc.w += v.w;
    }
    *(float4*)(g_Ppart + b * 1024 + t * 4) = acc;
}

// ---------------- K_thr: thresholds (b0) + weight masks (b1-4) + alpha ----
__global__ __launch_bounds__(1024) void k_thr(const float* __restrict__ w1,
                                              const float* __restrict__ w2,
                                              const float* __restrict__ wl) {
    int b = blockIdx.x, t = threadIdx.x;
    if (b == 0) {
        __shared__ double Ps[1024];
        __shared__ double Ts[25];
        double s0 = 0.0, s1 = 0.0;
        for (int i = 0; i < 128; i += 2) {
            s0 += (double)g_Ppart[i * 1024 + t];
            s1 += (double)g_Ppart[(i + 1) * 1024 + t];
        }
        Ps[t] = s0 + s1;
        __syncthreads();
        if (t < 800) {                // 25 taps x 32 lanes, fixed shfl tree
            int g = t >> 5, lane = t & 31;
            int dy = g / 5, dx = g % 5;
            double a = 0.0;
            for (int idx = lane; idx < 784; idx += 32) {
                int i = idx / 28, j = idx % 28;
                a += Ps[(i + dy) * 32 + (j + dx)];
            }
#pragma unroll
            for (int o = 16; o; o >>= 1) a += __shfl_down_sync(0xffffffffu, a, o);
            if (lane == 0) Ts[g] = a;
        }
        __syncthreads();
        if (t < 20) {
            double d = 0.0;
            for (int k = 0; k < 25; ++k) d += (double)w1[t * 25 + k] * Ts[k];
            g_thr[t] = (float)(d / (8192.0 * 28.0 * 28.0));
        }
    } else if (b < 5) {
        int gid = (b - 1) * 1024 + t;            // 0..4095
        if (gid < 1250) {                         // conv2 masks
            int oc = gid / 25, d = gid % 25;
            int dy = d / 5, dx = d % 5;
            unsigned mp = 0, mz = 0;
            for (int c = 0; c < 20; ++c) {
                float w = w2[oc * 500 + c * 25 + d];
                if (w > 0.f) mp |= 1u << c;
                else if (w == 0.f) mz |= 1u << c;
            }
            g_wz2[gid] = mz;
            g_wp2p[(oc * 5 + dy) * 8 + dx] = mp;
            if (dx == 0) {                        // zero the pad words
                g_wp2p[(oc * 5 + dy) * 8 + 5] = 0;
                g_wp2p[(oc * 5 + dy) * 8 + 6] = 0;
                g_wp2p[(oc * 5 + dy) * 8 + 7] = 0;
            }
            if (mz) atomicOr(&g_zflag2, 1);
        }
        for (int e = gid; e < 500 * 40; e += 4096) {  // linear masks
            int j = e / 40, wi = e % 40;
            unsigned mp = 0, mz = 0;
            for (int bit = 0; bit < 32; ++bit) {
                int i = wi * 32 + bit;
                if (i < 1250) {
                    float w = wl[j * 1250 + i];
                    if (w > 0.f) mp |= 1u << bit;
                    else if (w == 0.f) mz |= 1u << bit;
                }
            }
            g_wpl[e] = mp; g_wzl[e] = mz;
            if (mz) atomicOr(&g_zflagl, 1);
        }
    } else {
        int w = (b - 5) * 32 + (t >> 5);         // alpha_l row index, 16 blocks
        int lane = t & 31;
        if (w < 500) {
            double s = 0.0;
            for (int i = lane; i < 1250; i += 32)
                s += fabs((double)wl[w * 1250 + i]);
#pragma unroll
            for (int o = 16; o; o >>= 1) s += __shfl_down_sync(0xffffffffu, s, o);
            if (lane == 0) g_alphal[w] = (float)(s / 1250.0);
        }
    }
}

// ---------------- K_conv: fused conv1 + conv2 per 2 images ----------------
#define ROWW 20                       // padded row width (words)
__global__ __launch_bounds__(256) void k_conv(const float* __restrict__ x,
                                              const float* __restrict__ w1) {
    __shared__ __align__(16) float xs[2][1024];
    __shared__ __align__(16) float ws[20 * 40];   // 8-float padded rows
    __shared__ float thr_s[20];
    __shared__ unsigned b1s[2][196];
    __shared__ __align__(16) unsigned BsA[2 * 14 * ROWW];
    __shared__ __align__(16) unsigned BsB[2 * 14 * ROWW];
    __shared__ int PB[2][100];
    __shared__ __align__(16) unsigned Wps[50 * 5 * 8];
    __shared__ __align__(16) unsigned char sPN[2][1280];
    int n0 = blockIdx.x * 2, t = threadIdx.x;

    // --- stage conv1 weights (padded), thresholds, conv2 masks, images ---
    for (int i = t; i < 500; i += 256) {
        int c = i / 25, k = i % 25;
        ws[c * 40 + (k / 5) * 8 + (k % 5)] = w1[i];
    }
    if (t < 20) thr_s[t] = g_thr[t];
    for (int i = t; i < 2000; i += 256) Wps[i] = g_wp2p[i];
    if (t < 60) sPN[t / 30][1250 + (t % 30)] = 0;
    {
        const float* xb = x + (size_t)n0 * 1024;
        for (int i = t; i < 2048; i += 256) xs[0][i] = xb[i];   // [2][1024] linear
    }
    __syncthreads();

    // --- phase 1: conv1 + threshold + pool + bit-pack, flattened tasks ---
#pragma unroll 1
    for (int task = t; task < 392; task += 256) {
        int img = task >= 196;
        int p = task - img * 196;
        int py = p / 14, px = p % 14;
        float xp[6][6];
        const float* xb = &xs[img][(py * 2) * 32 + px * 2];
#pragma unroll
        for (int r = 0; r < 6; ++r) {
#pragma unroll
            for (int c2 = 0; c2 < 3; ++c2) {
                float2 v = *(const float2*)(xb + r * 32 + c2 * 2);
                xp[r][c2 * 2] = v.x; xp[r][c2 * 2 + 1] = v.y;
            }
        }
        unsigned word = 0;
#pragma unroll 1
        for (int c = 0; c < 20; ++c) {
            const float* wc = &ws[c * 40];
            float a0 = 0.f, a1 = 0.f, a2 = 0.f, a3 = 0.f;
#pragma unroll
            for (int dy = 0; dy < 5; ++dy) {
                float4 wq = *(const float4*)(wc + dy * 8);
                float w4 = wc[dy * 8 + 4];
                float wv[5] = {wq.x, wq.y, wq.z, wq.w, w4};
#pragma unroll
                for (int dx = 0; dx < 5; ++dx) {
                    float w = wv[dx];
                    a0 = fmaf(w, xp[dy][dx],         a0);
                    a1 = fmaf(w, xp[dy][dx + 1],     a1);
                    a2 = fmaf(w, xp[dy + 1][dx],     a2);
                    a3 = fmaf(w, xp[dy + 1][dx + 1], a3);
                }
            }
            float m = fmaxf(fmaxf(a0, a1), fmaxf(a2, a3));
            if (m > thr_s[c]) word |= (1u << c);
        }
        b1s[img][p] = word;
    }
    __syncthreads();

    // --- phase 2: XNOR conv2 on smem-resident bits (R8 layout) ---
    for (int i = t; i < 2 * 196; i += 256) {
        int img = i / 196, p = i % 196;
        int y = p / 14, xx = p % 14;
        unsigned bv = b1s[img][p];
        BsA[img * 14 * ROWW + y * ROWW + xx] = bv;
        if (xx >= 2) BsB[img * 14 * ROWW + y * ROWW + xx - 2] = bv;
    }
    __syncthreads();
    for (int i = t; i < 2 * 100; i += 256) {
        int img = i / 100, p = i % 100;
        int y = p / 10, xx = p % 10;
        const unsigned* B = &BsA[img * 14 * ROWW];
        int s = 0;
#pragma unroll
        for (int dy = 0; dy < 5; ++dy)
#pragma unroll
            for (int dx = 0; dx < 5; ++dx)
                s += __popc(B[(y + dy) * ROWW + xx + dx]);
        PB[img][p] = s;
    }
    __syncthreads();
    int zf = g_zflag2;
    if (t < 250) {
        int oc = t / 5, cx = t % 5;
        int odd = cx & 1;
        const unsigned* P0 = odd ? BsB : BsA;
        int colbase = odd ? (2 * cx - 2) : (2 * cx);
        unsigned W[25];
#pragma unroll
        for (int j = 0; j < 5; ++j) {
            uint4 wq = *(const uint4*)(&Wps[oc * 40 + j * 8]);
            W[j * 5] = wq.x; W[j * 5 + 1] = wq.y; W[j * 5 + 2] = wq.z; W[j * 5 + 3] = wq.w;
            W[j * 5 + 4] = Wps[oc * 40 + j * 8 + 4];
        }
#pragma unroll 1
        for (int r = 0; r < 5; ++r) {
#pragma unroll 1
            for (int img = 0; img < 2; ++img) {
                const unsigned* bp0 = P0 + img * 14 * ROWW + (2 * r) * ROWW + colbase;
                int a00 = 0, a01 = 0, a10 = 0, a11 = 0;
#pragma unroll
                for (int rr = 0; rr < 6; ++rr) {
                    const unsigned* bp = bp0 + rr * ROWW;
                    uint4 q = *(const uint4*)bp;
                    uint2 d2 = *(const uint2*)(bp + 4);
                    unsigned p0 = q.x, p1 = q.y, p2 = q.z, p3 = q.w, p4 = d2.x, p5 = d2.y;
                    if (rr < 5) {
                        a00 += __popc(p0 & W[rr * 5]) + __popc(p1 & W[rr * 5 + 1])
                             + __popc(p2 & W[rr * 5 + 2]) + __popc(p3 & W[rr * 5 + 3])
                             + __popc(p4 & W[rr * 5 + 4]);
                        a01 += __popc(p1 & W[rr * 5]) + __popc(p2 & W[rr * 5 + 1])
                             + __popc(p3 & W[rr * 5 + 2]) + __popc(p4 & W[rr * 5 + 3])
                             + __popc(p5 & W[rr * 5 + 4]);
                    }
                    if (rr >= 1) {
                        a10 += __popc(p0 & W[(rr - 1) * 5]) + __popc(p1 & W[(rr - 1) * 5 + 1])
                             + __popc(p2 & W[(rr - 1) * 5 + 2]) + __popc(p3 & W[(rr - 1) * 5 + 3])
                             + __popc(p4 & W[(rr - 1) * 5 + 4]);
                        a11 += __popc(p1 & W[(rr - 1) * 5]) + __popc(p2 & W[(rr - 1) * 5 + 1])
                             + __popc(p3 & W[(rr - 1) * 5 + 2]) + __popc(p4 & W[(rr - 1) * 5 + 3])
                             + __popc(p5 & W[(rr - 1) * 5 + 4]);
                    }
                }
                int v00 = 2 * a00 - PB[img][(2 * r) * 10 + 2 * cx];
                int v01 = 2 * a01 - PB[img][(2 * r) * 10 + 2 * cx + 1];
                int v10 = 2 * a10 - PB[img][(2 * r + 1) * 10 + 2 * cx];
                int v11 = 2 * a11 - PB[img][(2 * r + 1) * 10 + 2 * cx + 1];
                if (zf) {  // uniform, never taken with this dataset
                    const unsigned* B = &BsA[img * 14 * ROWW + (2 * r) * ROWW + 2 * cx];
                    int z00 = 0, z01 = 0, z10 = 0, z11 = 0;
                    for (int dy = 0; dy < 5; ++dy)
                        for (int dx = 0; dx < 5; ++dx) {
                            unsigned wz = g_wz2[oc * 25 + dy * 5 + dx];
                            z00 += __popc(B[dy * ROWW + dx] & wz);
                            z01 += __popc(B[dy * ROWW + dx + 1] & wz);
                            z10 += __popc(B[(dy + 1) * ROWW + dx] & wz);
                            z11 += __popc(B[(dy + 1) * ROWW + dx + 1] & wz);
                        }
                    v00 += z00; v01 += z01; v10 += z10; v11 += z11;
                }
                int best = max(max(v00, v01), max(v10, v11));
                sPN[img][oc * 25 + r * 5 + cx] =
                    (unsigned char)((best > 0 ? 1 : 0) | (best < 0 ? 2 : 0));
            }
        }
    }
    __syncthreads();
    if (t < 2 * 40) {                    // byte planes -> bit planes
        int img = t / 40, wi = t % 40;
        const unsigned* src = (const unsigned*)&sPN[img][0] + wi * 8;
        unsigned P = 0, N = 0;
#pragma unroll
        for (int j = 0; j < 8; ++j) {
            unsigned b = src[j];
            P |= ((((b & 0x01010101u) * 0x00204081u) >> 21) & 0xFu) << (4 * j);
            N |= (((((b >> 1) & 0x01010101u) * 0x00204081u) >> 21) & 0xFu) << (4 * j);
        }
        g_Bp[(size_t)(n0 + img) * 40 + wi] = P;
        g_Bn[(size_t)(n0 + img) * 40 + wi] = N;
    }
}

// ---------------- K4: binary linear + clip + fc — W streamed from gmem ----
#define D_IMGS 16
__global__ __launch_bounds__(512, 2) void k_dense(const float* __restrict__ fcw,
                                                  const float* __restrict__ fcb,
                                                  float* __restrict__ out) {
    __shared__ __align__(16) unsigned Bps[D_IMGS * 40];
    __shared__ __align__(16) unsigned Bns[D_IMGS * 40];
    __shared__ __align__(16) unsigned Us[D_IMGS * 40];
    __shared__ int pcU[D_IMGS];
    __shared__ float hs[D_IMGS * 500];
    int t = threadIdx.x;
    int n0 = blockIdx.x * D_IMGS;
    for (int i = t; i < D_IMGS * 40; i += 512) {
        int img = i / 40, wi = i % 40;
        unsigned bp = g_Bp[(size_t)(n0 + img) * 40 + wi];
        unsigned bn = g_Bn[(size_t)(n0 + img) * 40 + wi];
        Bps[img * 40 + wi] = bp;
        Bns[img * 40 + wi] = bn;
        Us[img * 40 + wi]  = bp | bn;
    }
    __syncthreads();
    if (t < D_IMGS) {
        int s = 0;
        for (int k = 0; k < 40; ++k) s += __popc(Us[t * 40 + k]);
        pcU[t] = s;
    }
    __syncthreads();
    int zf = g_zflagl;
    for (int j = t; j < 500; j += 512) {
        float al = g_alphal[j];
        int m[D_IMGS];
#pragma unroll
        for (int img = 0; img < D_IMGS; ++img) m[img] = 0;
#pragma unroll 1
        for (int half = 0; half < 2; ++half) {
            unsigned wr[20];
#pragma unroll
            for (int k = 0; k < 5; ++k) {
                uint4 q = *(const uint4*)(&g_wpl[j * 40 + half * 20 + k * 4]);
                wr[k * 4] = q.x; wr[k * 4 + 1] = q.y;
                wr[k * 4 + 2] = q.z; wr[k * 4 + 3] = q.w;
            }
#pragma unroll
            for (int img = 0; img < D_IMGS; ++img) {
                const unsigned* Bb = &Bps[img * 40 + half * 20];
                const unsigned* Ub = &Us[img * 40 + half * 20];
                int mm = 0;
#pragma unroll
                for (int k = 0; k < 5; ++k) {
                    uint4 bq = *(const uint4*)(Bb + k * 4);
                    uint4 uq = *(const uint4*)(Ub + k * 4);
                    mm += __popc((~(bq.x ^ wr[k * 4]))     & uq.x);
                    mm += __popc((~(bq.y ^ wr[k * 4 + 1])) & uq.y);
                    mm += __popc((~(bq.z ^ wr[k * 4 + 2])) & uq.z);
                    mm += __popc((~(bq.w ^ wr[k * 4 + 3])) & uq.w);
                }
                m[img] += mm;
            }
        }
#pragma unroll
        for (int img = 0; img < D_IMGS; ++img) {
            int vi = 2 * m[img] - pcU[img];
            if (zf) {  // uniform, never taken with this dataset
                int cp = 0, cn = 0;
                for (int k = 0; k < 40; ++k) {
                    unsigned z = g_wzl[j * 40 + k];
                    cp += __popc(Bps[img * 40 + k] & z);
                    cn += __popc(Bns[img * 40 + k] & z);
                }
                vi += cp - cn;
            }
            float h = fminf(fmaxf((float)vi * al, -1.f), 1.f);
            hs[img * 500 + j] = h;
        }
    }
    __syncthreads();
    int w = t >> 5, lane = t & 31;   // warp w -> image w
    for (int lg = 0; lg < 10; ++lg) {
        float p = 0.f;
        for (int j = lane; j < 500; j += 32)
            p += hs[w * 500 + j] * __ldg(&fcw[lg * 500 + j]);
#pragma unroll
        for (int o = 16; o; o >>= 1) p += __shfl_down_sync(0xffffffffu, p, o);
        if (lane == 0) out[(size_t)(n0 + w) * 10 + lg] = p + fcb[lg];
    }
}

// ---------------- launch ---------------------------------------------------
extern "C" void kernel_launch(void* const* d_in, const int* in_sizes, int n_in,
                              void* d_out, int out_size) {
    const float* x   = (const float*)d_in[0];
    const float* w1  = (const float*)d_in[1];
    const float* w2  = (const float*)d_in[2];
    const float* wl  = (const float*)d_in[3];
    const float* fcw = (const float*)d_in[4];
    const float* fcb = (const float*)d_in[5];
    float* out = (float*)d_out;

    k_pre<<<128, 256>>>(x);
    k_thr<<<21, 1024>>>(w1, w2, wl);
    k_conv<<<N_IMG / 2, 256>>>(x, w1);
    k_dense<<<N_IMG / D_IMGS, 512>>>(fcw, fcb, out);
}